// round 1
// baseline (speedup 1.0000x reference)
#include <cuda_runtime.h>
#include <math.h>

#define ENT_DIM   128
#define BATCH     262144
#define MARGIN    1.0f
#define EPS_V     1e-6f

// one warp per batch element; lane l owns dims [4l, 4l+4)
__device__ __forceinline__ float warp_score(
    float4 h, float4 hp, float4 t, float4 tp, float4 r, float4 rp)
{
    // per-lane partial dots
    float sh = hp.x * h.x + hp.y * h.y + hp.z * h.z + hp.w * h.w;
    float st = tp.x * t.x + tp.y * t.y + tp.z * t.z + tp.w * t.w;
    // butterfly reduce both dots together
    #pragma unroll
    for (int o = 16; o > 0; o >>= 1) {
        sh += __shfl_xor_sync(0xFFFFFFFFu, sh, o);
        st += __shfl_xor_sync(0xFFFFFFFFu, st, o);
    }
    float ds = sh - st;
    float dx = fmaf(rp.x, ds, h.x - t.x + r.x + EPS_V);
    float dy = fmaf(rp.y, ds, h.y - t.y + r.y + EPS_V);
    float dz = fmaf(rp.z, ds, h.z - t.z + r.z + EPS_V);
    float dw = fmaf(rp.w, ds, h.w - t.w + r.w + EPS_V);
    float ss = dx * dx + dy * dy + dz * dz + dw * dw;
    #pragma unroll
    for (int o = 16; o > 0; o >>= 1)
        ss += __shfl_xor_sync(0xFFFFFFFFu, ss, o);
    return sqrtf(ss);
}

__global__ void zero_out_kernel(float* out) { out[0] = 0.0f; }

__global__ __launch_bounds__(256, 4)
void transd_kernel(const float* __restrict__ ent,
                   const float* __restrict__ entp,
                   const float* __restrict__ rel,
                   const float* __restrict__ relp,
                   const int*   __restrict__ pos,
                   const int*   __restrict__ neg,
                   float*       __restrict__ out)
{
    const int lane   = threadIdx.x & 31;
    const int warp   = threadIdx.x >> 5;          // 0..7
    const int gwarp  = blockIdx.x * 8 + warp;     // batch element

    float val = 0.0f;
    if (gwarp < BATCH) {
        // indices (uniform loads, broadcast in L1)
        const int ph = pos[gwarp * 3 + 0];
        const int pr = pos[gwarp * 3 + 1];
        const int pt = pos[gwarp * 3 + 2];
        const int nh = neg[gwarp * 3 + 0];
        const int nr = neg[gwarp * 3 + 1];
        const int nt = neg[gwarp * 3 + 2];

        const size_t lo = (size_t)lane;  // float4 index within row

        // issue all 12 row gathers up front (MLP)
        const float4* E  = (const float4*)ent;
        const float4* EP = (const float4*)entp;
        const float4* R  = (const float4*)rel;
        const float4* RP = (const float4*)relp;

        float4 p_h  = E [(size_t)ph * 32 + lo];
        float4 p_hp = EP[(size_t)ph * 32 + lo];
        float4 p_t  = E [(size_t)pt * 32 + lo];
        float4 p_tp = EP[(size_t)pt * 32 + lo];
        float4 p_r  = R [(size_t)pr * 32 + lo];
        float4 p_rp = RP[(size_t)pr * 32 + lo];

        float4 n_h  = E [(size_t)nh * 32 + lo];
        float4 n_hp = EP[(size_t)nh * 32 + lo];
        float4 n_t  = E [(size_t)nt * 32 + lo];
        float4 n_tp = EP[(size_t)nt * 32 + lo];
        float4 n_r  = R [(size_t)nr * 32 + lo];
        float4 n_rp = RP[(size_t)nr * 32 + lo];

        float ps = warp_score(p_h, p_hp, p_t, p_tp, p_r, p_rp);
        float ns = warp_score(n_h, n_hp, n_t, n_tp, n_r, n_rp);

        float loss = ps - ns + MARGIN;
        val = loss > 0.0f ? loss : 0.0f;
    }

    // block reduction: lane 0 of each warp writes partial
    __shared__ float smem[8];
    if (lane == 0) smem[warp] = val;
    __syncthreads();
    if (warp == 0) {
        float s = (lane < 8) ? smem[lane] : 0.0f;
        #pragma unroll
        for (int o = 4; o > 0; o >>= 1)
            s += __shfl_xor_sync(0xFFFFFFFFu, s, o);
        if (lane == 0)
            atomicAdd(out, s * (1.0f / (float)BATCH));
    }
}

extern "C" void kernel_launch(void* const* d_in, const int* in_sizes, int n_in,
                              void* d_out, int out_size)
{
    const float* ent   = (const float*)d_in[0];
    const float* entp  = (const float*)d_in[1];
    const float* rel   = (const float*)d_in[2];
    const float* relp  = (const float*)d_in[3];
    const int*   pos_x = (const int*)d_in[4];
    const int*   neg_x = (const int*)d_in[5];
    float*       out   = (float*)d_out;

    zero_out_kernel<<<1, 1>>>(out);
    // 8 warps per block, one warp per batch element
    const int blocks = BATCH / 8;  // 32768
    transd_kernel<<<blocks, 256>>>(ent, entp, rel, relp, pos_x, neg_x, out);
}

// round 3
// speedup vs baseline: 1.0564x; 1.0564x over previous
#include <cuda_runtime.h>
#include <math.h>

#define ENT_DIM   128
#define BATCH     262144
#define MARGIN    1.0f
#define EPS_V     1e-6f

// 16B vector load, non-coherent, with L2 evict_last cache-hint policy
// (keeps entity lines resident in L2 for duplicate-index reuse).
__device__ __forceinline__ float4 ldg_el(const float4* p) {
    float4 v;
    asm volatile(
        "{\n\t"
        ".reg .b64 pol;\n\t"
        "createpolicy.fractional.L2::evict_last.b64 pol, 1.0;\n\t"
        "ld.global.nc.L2::cache_hint.v4.f32 {%0,%1,%2,%3}, [%4], pol;\n\t"
        "}"
        : "=f"(v.x), "=f"(v.y), "=f"(v.z), "=f"(v.w)
        : "l"(p));
    return v;
}

__device__ __forceinline__ float dot4(float4 a, float4 b) {
    return fmaf(a.x, b.x, fmaf(a.y, b.y, fmaf(a.z, b.z, a.w * b.w)));
}

__global__ __launch_bounds__(256, 4)
void transd_kernel(const float* __restrict__ ent,
                   const float* __restrict__ entp,
                   const float* __restrict__ rel,
                   const float* __restrict__ relp,
                   const int*   __restrict__ pos,
                   const int*   __restrict__ neg,
                   float*       __restrict__ out)
{
    const int lane  = threadIdx.x & 31;
    const int warp  = threadIdx.x >> 5;       // 0..7
    const int gwarp = blockIdx.x * 8 + warp;  // batch element

    // indices (uniform per warp)
    const int ph = pos[gwarp * 3 + 0];
    const int pr = pos[gwarp * 3 + 1];
    const int pt = pos[gwarp * 3 + 2];
    const int nh = neg[gwarp * 3 + 0];
    const int nr = neg[gwarp * 3 + 1];
    const int nt = neg[gwarp * 3 + 2];

    const size_t lo = (size_t)lane;

    const float4* E  = (const float4*)ent;
    const float4* EP = (const float4*)entp;
    const float4* R  = (const float4*)rel;
    const float4* RP = (const float4*)relp;

    // issue all 12 row gathers up front (MLP); entity rows get evict_last
    float4 p_h  = ldg_el(E  + (size_t)ph * 32 + lo);
    float4 p_hp = ldg_el(EP + (size_t)ph * 32 + lo);
    float4 p_t  = ldg_el(E  + (size_t)pt * 32 + lo);
    float4 p_tp = ldg_el(EP + (size_t)pt * 32 + lo);
    float4 n_h  = ldg_el(E  + (size_t)nh * 32 + lo);
    float4 n_hp = ldg_el(EP + (size_t)nh * 32 + lo);
    float4 n_t  = ldg_el(E  + (size_t)nt * 32 + lo);
    float4 n_tp = ldg_el(EP + (size_t)nt * 32 + lo);
    float4 p_r  = __ldg(R  + (size_t)pr * 32 + lo);
    float4 p_rp = __ldg(RP + (size_t)pr * 32 + lo);
    float4 n_r  = __ldg(R  + (size_t)nr * 32 + lo);
    float4 n_rp = __ldg(RP + (size_t)nr * 32 + lo);

    // four dot partials, one fused butterfly chain
    float psh = dot4(p_hp, p_h);
    float pst = dot4(p_tp, p_t);
    float nsh = dot4(n_hp, n_h);
    float nst = dot4(n_tp, n_t);
    #pragma unroll
    for (int o = 16; o > 0; o >>= 1) {
        psh += __shfl_xor_sync(0xFFFFFFFFu, psh, o);
        pst += __shfl_xor_sync(0xFFFFFFFFu, pst, o);
        nsh += __shfl_xor_sync(0xFFFFFFFFu, nsh, o);
        nst += __shfl_xor_sync(0xFFFFFFFFu, nst, o);
    }
    const float pds = psh - pst;
    const float nds = nsh - nst;

    // d vectors + squared partials, fused butterfly
    float pdx = fmaf(p_rp.x, pds, p_h.x - p_t.x + p_r.x + EPS_V);
    float pdy = fmaf(p_rp.y, pds, p_h.y - p_t.y + p_r.y + EPS_V);
    float pdz = fmaf(p_rp.z, pds, p_h.z - p_t.z + p_r.z + EPS_V);
    float pdw = fmaf(p_rp.w, pds, p_h.w - p_t.w + p_r.w + EPS_V);
    float ndx = fmaf(n_rp.x, nds, n_h.x - n_t.x + n_r.x + EPS_V);
    float ndy = fmaf(n_rp.y, nds, n_h.y - n_t.y + n_r.y + EPS_V);
    float ndz = fmaf(n_rp.z, nds, n_h.z - n_t.z + n_r.z + EPS_V);
    float ndw = fmaf(n_rp.w, nds, n_h.w - n_t.w + n_r.w + EPS_V);

    float pss = pdx*pdx + pdy*pdy + pdz*pdz + pdw*pdw;
    float nss = ndx*ndx + ndy*ndy + ndz*ndz + ndw*ndw;
    #pragma unroll
    for (int o = 16; o > 0; o >>= 1) {
        pss += __shfl_xor_sync(0xFFFFFFFFu, pss, o);
        nss += __shfl_xor_sync(0xFFFFFFFFu, nss, o);
    }

    float loss = sqrtf(pss) - sqrtf(nss) + MARGIN;
    float val = loss > 0.0f ? loss : 0.0f;

    // block reduction: lane 0 of each warp writes partial
    __shared__ float smem[8];
    if (lane == 0) smem[warp] = val;
    __syncthreads();
    if (warp == 0) {
        float s = (lane < 8) ? smem[lane] : 0.0f;
        #pragma unroll
        for (int o = 4; o > 0; o >>= 1)
            s += __shfl_xor_sync(0xFFFFFFFFu, s, o);
        if (lane == 0)
            atomicAdd(out, s * (1.0f / (float)BATCH));
    }
}

extern "C" void kernel_launch(void* const* d_in, const int* in_sizes, int n_in,
                              void* d_out, int out_size)
{
    const float* ent   = (const float*)d_in[0];
    const float* entp  = (const float*)d_in[1];
    const float* rel   = (const float*)d_in[2];
    const float* relp  = (const float*)d_in[3];
    const int*   pos_x = (const int*)d_in[4];
    const int*   neg_x = (const int*)d_in[5];
    float*       out   = (float*)d_out;

    // graph-capturable memset node (cheaper than a zeroing kernel launch)
    cudaMemsetAsync(out, 0, sizeof(float));

    const int blocks = BATCH / 8;  // one warp per batch element
    transd_kernel<<<blocks, 256>>>(ent, entp, rel, relp, pos_x, neg_x, out);
}

// round 4
// speedup vs baseline: 1.0853x; 1.0273x over previous
#include <cuda_runtime.h>
#include <math.h>

#define BATCH     262144
#define MARGIN    1.0f
#define EPS_V     1e-6f

// 16B vector load, non-coherent, with L2 evict_last cache-hint policy.
__device__ __forceinline__ float4 ldg_el(const float4* p) {
    float4 v;
    asm volatile(
        "{\n\t"
        ".reg .b64 pol;\n\t"
        "createpolicy.fractional.L2::evict_last.b64 pol, 1.0;\n\t"
        "ld.global.nc.L2::cache_hint.v4.f32 {%0,%1,%2,%3}, [%4], pol;\n\t"
        "}"
        : "=f"(v.x), "=f"(v.y), "=f"(v.z), "=f"(v.w)
        : "l"(p));
    return v;
}

__device__ __forceinline__ float dot4(float4 a, float4 b) {
    return fmaf(a.x, b.x, fmaf(a.y, b.y, fmaf(a.z, b.z, a.w * b.w)));
}

// One warp per triple (pos OR neg). Even warp = pos side of element,
// odd warp = neg side of same element. 6 row-gathers per warp -> ~half the
// registers of the 12-gather version -> 6 blocks/SM resident.
__global__ __launch_bounds__(256, 6)
void transd_kernel(const float* __restrict__ ent,
                   const float* __restrict__ entp,
                   const float* __restrict__ rel,
                   const float* __restrict__ relp,
                   const int*   __restrict__ pos,
                   const int*   __restrict__ neg,
                   float*       __restrict__ out)
{
    const int lane = threadIdx.x & 31;
    const int warp = threadIdx.x >> 5;          // 0..7
    const int pair = warp >> 1;                 // 0..3 element within block
    const int elem = blockIdx.x * 4 + pair;     // batch element
    const bool is_neg = warp & 1;

    const int* __restrict__ tri = is_neg ? neg : pos;
    const int h = tri[elem * 3 + 0];
    const int r = tri[elem * 3 + 1];
    const int t = tri[elem * 3 + 2];

    const size_t lo = (size_t)lane;
    const float4* E  = (const float4*)ent;
    const float4* EP = (const float4*)entp;
    const float4* R  = (const float4*)rel;
    const float4* RP = (const float4*)relp;

    // all 6 gathers issued up front
    float4 vh  = ldg_el(E  + (size_t)h * 32 + lo);
    float4 vhp = ldg_el(EP + (size_t)h * 32 + lo);
    float4 vt  = ldg_el(E  + (size_t)t * 32 + lo);
    float4 vtp = ldg_el(EP + (size_t)t * 32 + lo);
    float4 vr  = __ldg(R  + (size_t)r * 32 + lo);
    float4 vrp = __ldg(RP + (size_t)r * 32 + lo);

    // two dot partials, fused butterfly
    float sh = dot4(vhp, vh);
    float st = dot4(vtp, vt);
    #pragma unroll
    for (int o = 16; o > 0; o >>= 1) {
        sh += __shfl_xor_sync(0xFFFFFFFFu, sh, o);
        st += __shfl_xor_sync(0xFFFFFFFFu, st, o);
    }
    const float ds = sh - st;

    float dx = fmaf(vrp.x, ds, vh.x - vt.x + vr.x + EPS_V);
    float dy = fmaf(vrp.y, ds, vh.y - vt.y + vr.y + EPS_V);
    float dz = fmaf(vrp.z, ds, vh.z - vt.z + vr.z + EPS_V);
    float dw = fmaf(vrp.w, ds, vh.w - vt.w + vr.w + EPS_V);

    float ss = dx*dx + dy*dy + dz*dz + dw*dw;
    #pragma unroll
    for (int o = 16; o > 0; o >>= 1)
        ss += __shfl_xor_sync(0xFFFFFFFFu, ss, o);

    const float score = sqrtf(ss);

    // pair-exchange via shared, then block-level accumulate
    __shared__ float scores[8];
    if (lane == 0) scores[warp] = score;
    __syncthreads();

    if (warp == 0) {
        float s = 0.0f;
        if (lane < 4) {
            float loss = scores[2 * lane] - scores[2 * lane + 1] + MARGIN;
            s = loss > 0.0f ? loss : 0.0f;
        }
        #pragma unroll
        for (int o = 2; o > 0; o >>= 1)
            s += __shfl_xor_sync(0xFFFFFFFFu, s, o);
        if (lane == 0)
            atomicAdd(out, s * (1.0f / (float)BATCH));
    }
}

extern "C" void kernel_launch(void* const* d_in, const int* in_sizes, int n_in,
                              void* d_out, int out_size)
{
    const float* ent   = (const float*)d_in[0];
    const float* entp  = (const float*)d_in[1];
    const float* rel   = (const float*)d_in[2];
    const float* relp  = (const float*)d_in[3];
    const int*   pos_x = (const int*)d_in[4];
    const int*   neg_x = (const int*)d_in[5];
    float*       out   = (float*)d_out;

    cudaMemsetAsync(out, 0, sizeof(float));

    // 4 elements per block (8 warps, one triple per warp)
    const int blocks = BATCH / 4;  // 65536
    transd_kernel<<<blocks, 256>>>(ent, entp, rel, relp, pos_x, neg_x, out);
}